// round 3
// baseline (speedup 1.0000x reference)
#include <cuda_runtime.h>
#include <math.h>

#define BB 4
#define SS 2048
#define DD 1024
#define BD (BB*DD)          // 4096
#define MT (BB*SS)          // 8192
#define CH 128
#define NC (SS/CH)          // 16

#define RP   128            // persistent CTAs in recurrence
#define RR   (DD/RP)        // 8 rows per CTA

typedef unsigned long long ull;

// ------------------------- scratch (device globals; no allocation) ---------
__device__ float g_ret[(size_t)MT*DD];
__device__ float g_inp[(size_t)MT*DD];
__device__ float g_gl [(size_t)MT*DD];
__device__ float g_ct [(size_t)MT*DD];
__device__ float g_st [(size_t)MT*DD];
__device__ float g_chend[BD*NC];
__device__ float g_carry[BD*NC];
__device__ float g_blend[2*BD];
__device__ unsigned g_flags[RP];

// ------------------------- small helpers ------------------------------------
__device__ __forceinline__ void ffma2(ull& d, ull a, ull b) {
    asm volatile("fma.rn.f32x2 %0, %1, %2, %0;" : "+l"(d) : "l"(a), "l"(b));
}
__device__ __forceinline__ float2 unpack2(ull v) {
    float2 f; asm("mov.b64 {%0, %1}, %2;" : "=f"(f.x), "=f"(f.y) : "l"(v)); return f;
}
__device__ __forceinline__ void st_release(unsigned* p, unsigned v) {
    asm volatile("st.release.gpu.global.u32 [%0], %1;" :: "l"(p), "r"(v) : "memory");
}
__device__ __forceinline__ unsigned ld_acquire(const unsigned* p) {
    unsigned v;
    asm volatile("ld.acquire.gpu.global.u32 %0, [%1];" : "=r"(v) : "l"(p) : "memory");
    return v;
}
__device__ __forceinline__ void cp_async16(unsigned dst, const void* src) {
    asm volatile("cp.async.cg.shared.global [%0], [%1], 16;" :: "r"(dst), "l"(src));
}
#define CP_COMMIT() asm volatile("cp.async.commit_group;")
#define CP_WAIT1()  asm volatile("cp.async.wait_group 1;")

__device__ __forceinline__ float fsigmoid(float x) {
    float e = __expf(-x);
    return __fdividef(1.f, 1.f + e);
}
__device__ __forceinline__ float ftanh(float x) {
    x = fminf(fmaxf(x, -15.f), 15.f);
    float e = __expf(2.f * x);
    return __fdividef(e - 1.f, e + 1.f);
}

// ------------------------- misc ---------------------------------------------
__global__ void k_reset() { if (threadIdx.x < RP) g_flags[threadIdx.x] = 0u; }

// ------------------------- retention scan (chunked parallel scan) ----------
__global__ void k_scan1(const float* __restrict__ k, const float* __restrict__ v,
                        const float* __restrict__ decay)
{
    int g = blockIdx.x * blockDim.x + threadIdx.x;
    int d    = g & (DD-1);
    int rest = g >> 10;
    int ch   = rest & (NC-1);
    int b    = rest >> 4;
    float dec = decay[d >> 6];
    size_t base = ((size_t)(b*SS + ch*CH))*DD + d;
    float r = 0.f;
#pragma unroll 4
    for (int t = 0; t < CH; t++) {
        r = dec*r + k[base + (size_t)t*DD] * v[base + (size_t)t*DD];
    }
    g_chend[(b*NC + ch)*DD + d] = r;
}

__global__ void k_scan2(const float* __restrict__ decay)
{
    int g = blockIdx.x * blockDim.x + threadIdx.x;
    int d = g & (DD-1);
    int b = g >> 10;
    float dec = decay[d >> 6];
    float dL = dec;
#pragma unroll
    for (int i = 0; i < 7; i++) dL *= dL;   // dec^128
    float r = 0.f;
#pragma unroll
    for (int ch = 0; ch < NC; ch++) {
        g_carry[(b*NC + ch)*DD + d] = r;
        r = g_chend[(b*NC + ch)*DD + d] + dL * r;
    }
}

__global__ void k_scan3(const float* __restrict__ q, const float* __restrict__ k,
                        const float* __restrict__ v, const float* __restrict__ decay)
{
    int g = blockIdx.x * blockDim.x + threadIdx.x;
    int d    = g & (DD-1);
    int rest = g >> 10;
    int ch   = rest & (NC-1);
    int b    = rest >> 4;
    float dec = decay[d >> 6];
    float r = g_carry[(b*NC + ch)*DD + d];
    size_t base = ((size_t)(b*SS + ch*CH))*DD + d;
#pragma unroll 4
    for (int t = 0; t < CH; t++) {
        size_t o = base + (size_t)t*DD;
        r = dec*r + k[o]*v[o];
        g_ret[o] = q[o]*r;
    }
}

// ------------------------- fp32 GEMM via packed f32x2 -----------------------
// C[M,N] = Act[M,K] @ W[N,K]^T (+bias).  128x128x16 tiles, 256 threads.
// k-pair packed accumulators (FFMA2), row-major smem tiles fed by cp.async,
// double-buffered. micro: m = tr*8+i (i<8), n = tc+16g (g<8).
#define GBK 16
#define BSTR 20   // Bs row stride in floats (16B-aligned, low bank conflict)

__global__ __launch_bounds__(256)
void k_gemm(const float* __restrict__ Act, const float* __restrict__ W,
            const float* __restrict__ bias, float* __restrict__ C,
            int M, int N, int K, int hasBias)
{
    __shared__ float As[2][128*GBK];
    __shared__ float Bs[2][128*BSTR];
    int tid = threadIdx.x;
    int tr = tid >> 4, tc = tid & 15;
    const float* Ab = Act + (size_t)blockIdx.y * 128 * K;
    const float* Wb = W   + (size_t)blockIdx.x * 128 * K;

    unsigned sA0 = (unsigned)__cvta_generic_to_shared(&As[0][0]);
    unsigned sB0 = (unsigned)__cvta_generic_to_shared(&Bs[0][0]);

    ull acc[8][8];
#pragma unroll
    for (int i = 0; i < 8; i++)
#pragma unroll
        for (int g = 0; g < 8; g++) acc[i][g] = 0ull;

    auto loadTile = [&](int buf, int k0) {
#pragma unroll
        for (int i2 = 0; i2 < 2; i2++) {
            int f   = tid + i2*256;          // 0..511
            int row = f >> 2;
            int c4  = (f & 3) * 4;
            cp_async16(sA0 + (unsigned)(buf*128*GBK  + row*GBK  + c4)*4u,
                       Ab + (size_t)row*K + k0 + c4);
            cp_async16(sB0 + (unsigned)(buf*128*BSTR + row*BSTR + c4)*4u,
                       Wb + (size_t)row*K + k0 + c4);
        }
    };

    int nk = K / GBK;
    loadTile(0, 0);
    CP_COMMIT();

    for (int kt = 0; kt < nk; kt++) {
        if (kt + 1 < nk) loadTile((kt+1) & 1, (kt+1)*GBK);
        CP_COMMIT();
        CP_WAIT1();
        __syncthreads();

        const float* Abs = &As[kt & 1][0];
        const float* Bbs = &Bs[kt & 1][0];
#pragma unroll
        for (int kk2 = 0; kk2 < GBK/2; kk2++) {
            ull a2[8], b2[8];
#pragma unroll
            for (int i = 0; i < 8; i++)
                a2[i] = *(const ull*)(Abs + (tr*8 + i)*GBK + kk2*2);
#pragma unroll
            for (int g = 0; g < 8; g++)
                b2[g] = *(const ull*)(Bbs + (tc + 16*g)*BSTR + kk2*2);
#pragma unroll
            for (int i = 0; i < 8; i++)
#pragma unroll
                for (int g = 0; g < 8; g++)
                    ffma2(acc[i][g], a2[i], b2[g]);
        }
        __syncthreads();
    }

    int mb = blockIdx.y*128 + tr*8;
    int nb = blockIdx.x*128 + tc;
#pragma unroll
    for (int g = 0; g < 8; g++) {
        int n = nb + 16*g;
        float bv = hasBias ? bias[n] : 0.f;
#pragma unroll
        for (int i = 0; i < 8; i++) {
            float2 p = unpack2(acc[i][g]);
            C[(size_t)(mb + i)*N + n] = (p.x + p.y) + bv;
        }
    }
}

// ------------------------- sequential state recurrence ----------------------
// 128 persistent CTAs x 256 threads (single wave). CTA owns 8 state rows x 4
// batches. Per step: warp0 publishes blended slice + release-flag; each warp
// acquire-polls only its 16 producer flags, stages its own 2KB k-chunk, runs a
// register-A FFMA2 GEMV; one __syncthreads; warp0 reduces + tanh + next blend.
// g_gl/g_inp/g_ct for t+1 are register-prefetched during step t.
__global__ __launch_bounds__(256, 1)
void k_recur(const float* __restrict__ Amat)
{
    __shared__ float bl_s[4][1032];   // padded: conflict-free GEMV broadcast
    __shared__ float part[8][32];

    int tid  = threadIdx.x;
    int cta  = blockIdx.x;
    int row0 = cta * RR;
    int w    = tid >> 5;              // warp = k-chunk of 128
    int lane = tid & 31;
    int lr   = lane >> 2;             // local row 0..7
    int bo   = lane & 3;              // batch 0..3

    // A slice in registers, k-pair packed: A[row0+lr][w*128 .. +127]
    ull a2[64];
    {
        const ulonglong2* Ar =
            (const ulonglong2*)(Amat + (size_t)(row0 + lr)*DD + w*128);
#pragma unroll
        for (int i = 0; i < 32; i++) {
            ulonglong2 u = Ar[i];
            a2[2*i]   = u.x;
            a2[2*i+1] = u.y;
        }
    }

    int b2 = tid & 3, l2 = tid >> 2;          // only meaningful for tid<32
    size_t idx0 = ((size_t)b2*SS)*DD + row0 + l2;
    float state = 0.f;
    float pf_gl = 0.f, pf_inp = 0.f, pf_ct = 0.f;
    if (tid < 32) {
        pf_gl  = __ldcs(&g_gl [idx0]);
        pf_inp = __ldcs(&g_inp[idx0]);
        pf_ct  = __ldcs(&g_ct [idx0]);
    }

    for (int t = 0; t < SS; t++) {
        // 1) warp 0: blend + publish + release flag, then prefetch t+1
        if (tid < 32) {
            float gate = fsigmoid(pf_gl);
            float bl = fmaf(gate, state - pf_inp, pf_inp);
            __stcg(&g_blend[(t & 1)*BD + b2*DD + row0 + l2], bl);
            __syncwarp();
            if (tid == 0) st_release(&g_flags[cta], (unsigned)(t + 1));
            int tn = (t + 1 < SS) ? t + 1 : t;
            pf_gl  = __ldcs(&g_gl [idx0 + (size_t)tn*DD]);
            pf_inp = __ldcs(&g_inp[idx0 + (size_t)tn*DD]);
        }

        // 2) each warp acquire-polls only its 16 producers
        {
            unsigned tgt = (unsigned)(t + 1);
            if (lane < 16) {
                const unsigned* fp = &g_flags[w*16 + lane];
                unsigned v0;
                do { v0 = ld_acquire(fp); } while (v0 < tgt);
            }
            __syncwarp();
        }

        // 3) stage this warp's 2KB chunk (L2 -> SMEM, L1-bypassed)
        {
            const float4* src = (const float4*)(g_blend + (t & 1)*BD);
#pragma unroll
            for (int j = 0; j < 4; j++) {
                float4 vv = __ldcg(src + (size_t)j*(DD/4) + w*32 + lane);
                *(float4*)&bl_s[j][w*128 + lane*4] = vv;
            }
            __syncwarp();
        }

        // 4) register-A GEMV over this warp's k-chunk (packed f32x2)
        {
            const ulonglong2* xb = (const ulonglong2*)&bl_s[bo][w*128];
            ull s0 = 0ull, s1 = 0ull;
#pragma unroll
            for (int i = 0; i < 32; i++) {
                ulonglong2 x = xb[i];
                ffma2(s0, a2[2*i],   x.x);
                ffma2(s1, a2[2*i+1], x.y);
            }
            float2 p0 = unpack2(s0), p1 = unpack2(s1);
            part[w][lane] = (p0.x + p0.y) + (p1.x + p1.y);
        }
        __syncthreads();

        // 5) warp 0: reduce 8 chunks, add Bm-term, tanh, commit state
        if (tid < 32) {
            float s = pf_ct;
#pragma unroll
            for (int ww = 0; ww < 8; ww++) s += part[ww][tid];
            state = ftanh(s);
            __stcg(&g_st[idx0 + (size_t)t*DD], state);
            int tn = (t + 1 < SS) ? t + 1 : t;
            pf_ct = __ldcs(&g_ct[idx0 + (size_t)tn*DD]);
        }
    }
}

// ------------------------- launch -------------------------------------------
extern "C" void kernel_launch(void* const* d_in, const int* in_sizes, int n_in,
                              void* d_out, int out_size)
{
    const float* q     = (const float*)d_in[0];
    const float* k     = (const float*)d_in[1];
    const float* v     = (const float*)d_in[2];
    const float* Wi    = (const float*)d_in[3];
    const float* bi    = (const float*)d_in[4];
    const float* Wg    = (const float*)d_in[5];
    const float* bg    = (const float*)d_in[6];
    const float* A     = (const float*)d_in[7];
    const float* Bm    = (const float*)d_in[8];
    const float* Wo    = (const float*)d_in[9];
    const float* bo    = (const float*)d_in[10];
    const float* decay = (const float*)d_in[11];
    float* out = (float*)d_out;

    void *p_ret, *p_inp, *p_gl, *p_ct, *p_st;
    cudaGetSymbolAddress(&p_ret, g_ret);
    cudaGetSymbolAddress(&p_inp, g_inp);
    cudaGetSymbolAddress(&p_gl,  g_gl);
    cudaGetSymbolAddress(&p_ct,  g_ct);
    cudaGetSymbolAddress(&p_st,  g_st);

    k_reset<<<1, 128>>>();

    k_scan1<<<(BD*NC)/256, 256>>>(k, v, decay);
    k_scan2<<<BD/256, 256>>>(decay);
    k_scan3<<<(BD*NC)/256, 256>>>(q, k, v, decay);

    dim3 gg(DD/128, MT/128);   // (N tiles, M tiles)
    // inp = retained @ Wi.T + bi
    k_gemm<<<gg, 256>>>((const float*)p_ret, Wi, bi, (float*)p_inp, MT, DD, DD, 1);
    // gate logits = inp @ Wg.T + bg
    k_gemm<<<gg, 256>>>((const float*)p_inp, Wg, bg, (float*)p_gl, MT, DD, DD, 1);
    // ct = inp @ Bm.T
    k_gemm<<<gg, 256>>>((const float*)p_inp, Bm, (const float*)0, (float*)p_ct, MT, DD, DD, 0);

    // sequential recurrence over S steps
    k_recur<<<RP, 256>>>(A);

    // out = state @ Wo.T + bo
    k_gemm<<<gg, 256>>>((const float*)p_st, Wo, bo, out, MT, DD, DD, 1);
}

// round 4
// speedup vs baseline: 1.0852x; 1.0852x over previous
#include <cuda_runtime.h>
#include <math.h>

#define BB 4
#define SS 2048
#define DD 1024
#define BD (BB*DD)          // 4096
#define MT (BB*SS)          // 8192
#define CH 128
#define NC (SS/CH)          // 16

#define RP   128            // persistent CTAs in recurrence
#define RR   (DD/RP)        // 8 rows per CTA

// ------------------------- scratch (device globals; no allocation) ---------
__device__ float g_ret[(size_t)MT*DD];
__device__ float g_inp[(size_t)MT*DD];
__device__ float g_gl [(size_t)MT*DD];
__device__ float g_ct [(size_t)MT*DD];
__device__ float g_st [(size_t)MT*DD];
__device__ float g_chend[BD*NC];
__device__ float g_carry[BD*NC];
__device__ float g_blend[2*BD];
__device__ unsigned g_flags[RP];

// ------------------------- helpers ------------------------------------------
__device__ __forceinline__ void st_release(unsigned* p, unsigned v) {
    asm volatile("st.release.gpu.global.u32 [%0], %1;" :: "l"(p), "r"(v) : "memory");
}
__device__ __forceinline__ unsigned ld_acquire(const unsigned* p) {
    unsigned v;
    asm volatile("ld.acquire.gpu.global.u32 %0, [%1];" : "=r"(v) : "l"(p) : "memory");
    return v;
}
__device__ __forceinline__ void cp_async16(unsigned dst, const void* src) {
    asm volatile("cp.async.cg.shared.global [%0], [%1], 16;" :: "r"(dst), "l"(src));
}
#define CP_COMMIT() asm volatile("cp.async.commit_group;")
#define CP_WAIT1()  asm volatile("cp.async.wait_group 1;")
#define CP_WAIT0()  asm volatile("cp.async.wait_group 0;")

__device__ __forceinline__ unsigned f2tf32(float x) {
    unsigned u; asm("cvt.rna.tf32.f32 %0, %1;" : "=r"(u) : "f"(x)); return u;
}
__device__ __forceinline__ void mma_tf32(float* c, const unsigned* a, const unsigned* b) {
    asm volatile(
        "mma.sync.aligned.m16n8k8.row.col.f32.tf32.tf32.f32 "
        "{%0,%1,%2,%3}, {%4,%5,%6,%7}, {%8,%9}, {%0,%1,%2,%3};"
        : "+f"(c[0]), "+f"(c[1]), "+f"(c[2]), "+f"(c[3])
        : "r"(a[0]), "r"(a[1]), "r"(a[2]), "r"(a[3]), "r"(b[0]), "r"(b[1]));
}
__device__ __forceinline__ float fsigmoid(float x) {
    return __fdividef(1.f, 1.f + __expf(-x));
}
__device__ __forceinline__ float ftanh(float x) {
    x = fminf(fmaxf(x, -15.f), 15.f);
    float e = __expf(2.f * x);
    return __fdividef(e - 1.f, e + 1.f);
}

// ------------------------- misc ---------------------------------------------
__global__ void k_reset() { if (threadIdx.x < RP) g_flags[threadIdx.x] = 0u; }

// ------------------------- retention scan (chunked parallel scan) ----------
__global__ void k_scan1(const float* __restrict__ k, const float* __restrict__ v,
                        const float* __restrict__ decay)
{
    int g = blockIdx.x * blockDim.x + threadIdx.x;
    int d    = g & (DD-1);
    int rest = g >> 10;
    int ch   = rest & (NC-1);
    int b    = rest >> 4;
    float dec = decay[d >> 6];
    size_t base = ((size_t)(b*SS + ch*CH))*DD + d;
    float r = 0.f;
#pragma unroll 4
    for (int t = 0; t < CH; t++) {
        r = dec*r + k[base + (size_t)t*DD] * v[base + (size_t)t*DD];
    }
    g_chend[(b*NC + ch)*DD + d] = r;
}

__global__ void k_scan2(const float* __restrict__ decay)
{
    int g = blockIdx.x * blockDim.x + threadIdx.x;
    int d = g & (DD-1);
    int b = g >> 10;
    float dec = decay[d >> 6];
    float dL = dec;
#pragma unroll
    for (int i = 0; i < 7; i++) dL *= dL;   // dec^128
    float r = 0.f;
#pragma unroll
    for (int ch = 0; ch < NC; ch++) {
        g_carry[(b*NC + ch)*DD + d] = r;
        r = g_chend[(b*NC + ch)*DD + d] + dL * r;
    }
}

__global__ void k_scan3(const float* __restrict__ q, const float* __restrict__ k,
                        const float* __restrict__ v, const float* __restrict__ decay)
{
    int g = blockIdx.x * blockDim.x + threadIdx.x;
    int d    = g & (DD-1);
    int rest = g >> 10;
    int ch   = rest & (NC-1);
    int b    = rest >> 4;
    float dec = decay[d >> 6];
    float r = g_carry[(b*NC + ch)*DD + d];
    size_t base = ((size_t)(b*SS + ch*CH))*DD + d;
#pragma unroll 4
    for (int t = 0; t < CH; t++) {
        size_t o = base + (size_t)t*DD;
        r = dec*r + k[o]*v[o];
        g_ret[o] = q[o]*r;
    }
}

// ------------------------- TF32-split tensor-core GEMM ----------------------
// C[M,N] = Act[M,K] @ W[N,K]^T (+bias).  CTA tile 128x128, K-chunk 16.
// 8 warps: wm = wid&3 (32 rows), wn = wid>>2 (64 cols). Per warp: 2 m16 x 8 n8.
// Split per operand: hi = tf32(x), lo = tf32(x - hi); acc += hi*hi+hi*lo+lo*hi.
// SMEM row stride 20 floats -> conflict-free for both A and B fragment reads.
#define GBK  16
#define GSTR 20

__global__ __launch_bounds__(256)
void k_gemm(const float* __restrict__ Act, const float* __restrict__ W,
            const float* __restrict__ bias, float* __restrict__ C,
            int M, int N, int K, int hasBias)
{
    __shared__ float As[2][128*GSTR];
    __shared__ float Bs[2][128*GSTR];
    int tid  = threadIdx.x;
    int wid  = tid >> 5;
    int lane = tid & 31;
    int g    = lane >> 2;        // groupID
    int tig  = lane & 3;         // thread in group
    int wm   = wid & 3;          // m-subtile (32 rows)
    int wn   = wid >> 2;         // n-subtile (64 cols)

    const float* Ab = Act + (size_t)blockIdx.y * 128 * K;
    const float* Wb = W   + (size_t)blockIdx.x * 128 * K;
    unsigned sA0 = (unsigned)__cvta_generic_to_shared(&As[0][0]);
    unsigned sB0 = (unsigned)__cvta_generic_to_shared(&Bs[0][0]);

    float acc[2][8][4];
#pragma unroll
    for (int mt = 0; mt < 2; mt++)
#pragma unroll
        for (int nt = 0; nt < 8; nt++)
#pragma unroll
            for (int i = 0; i < 4; i++) acc[mt][nt][i] = 0.f;

    auto loadTile = [&](int buf, int k0) {
        int f   = tid * 2;                 // 512 float4 per chunk pair
#pragma unroll
        for (int i2 = 0; i2 < 2; i2++) {
            int ff  = f + i2;              // 0..511
            int row = ff >> 2;
            int c4  = (ff & 3) * 4;
            cp_async16(sA0 + (unsigned)(buf*128*GSTR + row*GSTR + c4)*4u,
                       Ab + (size_t)row*K + k0 + c4);
            cp_async16(sB0 + (unsigned)(buf*128*GSTR + row*GSTR + c4)*4u,
                       Wb + (size_t)row*K + k0 + c4);
        }
    };

    int nk = K / GBK;
    loadTile(0, 0);
    CP_COMMIT();

    for (int kt = 0; kt < nk; kt++) {
        if (kt + 1 < nk) { loadTile((kt+1) & 1, (kt+1)*GBK); CP_COMMIT(); CP_WAIT1(); }
        else             { CP_WAIT0(); }
        __syncthreads();

        const float* Abs = &As[kt & 1][0];
        const float* Bbs = &Bs[kt & 1][0];
#pragma unroll
        for (int ks = 0; ks < GBK/8; ks++) {
            int kb = ks*8;
            unsigned ah[2][4], al[2][4];
#pragma unroll
            for (int mt = 0; mt < 2; mt++) {
                int rb = wm*32 + mt*16;
                float f0 = Abs[(rb + g    )*GSTR + kb + tig    ];
                float f1 = Abs[(rb + g + 8)*GSTR + kb + tig    ];
                float f2 = Abs[(rb + g    )*GSTR + kb + tig + 4];
                float f3 = Abs[(rb + g + 8)*GSTR + kb + tig + 4];
                ah[mt][0] = f2tf32(f0); al[mt][0] = f2tf32(f0 - __uint_as_float(ah[mt][0]));
                ah[mt][1] = f2tf32(f1); al[mt][1] = f2tf32(f1 - __uint_as_float(ah[mt][1]));
                ah[mt][2] = f2tf32(f2); al[mt][2] = f2tf32(f2 - __uint_as_float(ah[mt][2]));
                ah[mt][3] = f2tf32(f3); al[mt][3] = f2tf32(f3 - __uint_as_float(ah[mt][3]));
            }
            unsigned bh[8][2], bl[8][2];
#pragma unroll
            for (int nt = 0; nt < 8; nt++) {
                int nb = wn*64 + nt*8;
                float f0 = Bbs[(nb + g)*GSTR + kb + tig    ];
                float f1 = Bbs[(nb + g)*GSTR + kb + tig + 4];
                bh[nt][0] = f2tf32(f0); bl[nt][0] = f2tf32(f0 - __uint_as_float(bh[nt][0]));
                bh[nt][1] = f2tf32(f1); bl[nt][1] = f2tf32(f1 - __uint_as_float(bh[nt][1]));
            }
#pragma unroll
            for (int mt = 0; mt < 2; mt++)
#pragma unroll
                for (int nt = 0; nt < 8; nt++) {
                    mma_tf32(acc[mt][nt], ah[mt], bh[nt]);
                    mma_tf32(acc[mt][nt], ah[mt], bl[nt]);
                    mma_tf32(acc[mt][nt], al[mt], bh[nt]);
                }
        }
        __syncthreads();
    }

    // epilogue
#pragma unroll
    for (int mt = 0; mt < 2; mt++) {
        int r0 = blockIdx.y*128 + wm*32 + mt*16 + g;
#pragma unroll
        for (int nt = 0; nt < 8; nt++) {
            int c0 = blockIdx.x*128 + wn*64 + nt*8 + 2*tig;
            float b0 = hasBias ? bias[c0]     : 0.f;
            float b1 = hasBias ? bias[c0 + 1] : 0.f;
            float2 o0 = make_float2(acc[mt][nt][0] + b0, acc[mt][nt][1] + b1);
            float2 o1 = make_float2(acc[mt][nt][2] + b0, acc[mt][nt][3] + b1);
            *(float2*)(C + (size_t)r0      *N + c0) = o0;
            *(float2*)(C + (size_t)(r0 + 8)*N + c0) = o1;
        }
    }
}

// ------------------------- sequential state recurrence ----------------------
// R1 structure, but the grid barrier uses per-CTA release flags (distinct
// addresses, no atomic RMW serialization) polled by 128 threads via
// read-broadcast loads. gl/inp/ct prefetched one step ahead in registers.
__global__ __launch_bounds__(256, 1)
void k_recur(const float* __restrict__ Amat)
{
    __shared__ float bl_s[4][1032];   // padded: conflict-free GEMV broadcast
    __shared__ float part[8][32];

    int tid  = threadIdx.x;
    int cta  = blockIdx.x;
    int row0 = cta * RR;
    int w    = tid >> 5;              // warp = k-chunk of 128
    int lane = tid & 31;
    int lr   = lane >> 2;             // local row 0..7
    int bo   = lane & 3;              // batch 0..3

    // A slice into registers: A[row0+lr][w*128 .. w*128+127]
    float4 a4[32];
    {
        const float* Arow = Amat + (size_t)(row0 + lr)*DD + w*128;
#pragma unroll
        for (int i = 0; i < 32; i++) a4[i] = *(const float4*)(Arow + i*4);
    }

    int b2 = tid & 3, l2 = tid >> 2;          // meaningful for tid<32
    size_t idx0 = ((size_t)b2*SS)*DD + row0 + l2;
    float state = 0.f;
    float pf_gl = 0.f, pf_inp = 0.f, pf_ct = 0.f;
    if (tid < 32) {
        pf_gl  = g_gl [idx0];
        pf_inp = g_inp[idx0];
        pf_ct  = g_ct [idx0];
    }
    __syncthreads();

    for (int t = 0; t < SS; t++) {
        // 1) warp 0: blend + publish; prefetch t+1 gl/inp
        if (tid < 32) {
            float gate = fsigmoid(pf_gl);
            float bl = fmaf(gate, state - pf_inp, pf_inp);
            __stcg(&g_blend[(t & 1)*BD + b2*DD + row0 + l2], bl);
            int tn = (t + 1 < SS) ? t + 1 : t;
            pf_gl  = g_gl [idx0 + (size_t)tn*DD];
            pf_inp = g_inp[idx0 + (size_t)tn*DD];
        }
        __syncthreads();

        // 2) arrival: one release store per CTA (distinct address)
        if (tid == 0) {
            __threadfence();
            st_release(&g_flags[cta], (unsigned)(t + 1));
        }
        // wait: 128 threads each poll one flag (load broadcast, no RMW)
        if (tid < RP) {
            unsigned tgt = (unsigned)(t + 1);
            const unsigned* fp = &g_flags[tid];
            while (ld_acquire(fp) < tgt) { }
        }
        __syncthreads();

        // 3) stage full blended vector into SMEM (L1-bypassed)
        {
            const float4* src = (const float4*)(g_blend + (t & 1)*BD);
#pragma unroll
            for (int i = 0; i < 4; i++) {
                int idx = tid + i*256;            // 1024 float4
                float4 vv = __ldcg(src + idx);
                int bb = idx >> 8;
                int k4 = (idx & 255) * 4;
                *(float4*)&bl_s[bb][k4] = vv;
            }
        }
        __syncthreads();

        // 4) register-A GEMV over this warp's k-chunk
        {
            const float4* xb = (const float4*)&bl_s[bo][w*128];
            float s0 = 0.f, s1 = 0.f, s2 = 0.f, s3 = 0.f;
#pragma unroll
            for (int i = 0; i < 32; i++) {
                float4 x = xb[i];
                s0 = fmaf(a4[i].x, x.x, s0);
                s1 = fmaf(a4[i].y, x.y, s1);
                s2 = fmaf(a4[i].z, x.z, s2);
                s3 = fmaf(a4[i].w, x.w, s3);
            }
            part[w][lane] = (s0 + s1) + (s2 + s3);
        }
        __syncthreads();

        // 5) warp 0: reduce 8 chunks, add Bm-term, tanh, commit state
        if (tid < 32) {
            float s = pf_ct;
#pragma unroll
            for (int ww = 0; ww < 8; ww++) s += part[ww][tid];
            state = ftanh(s);
            __stcg(&g_st[idx0 + (size_t)t*DD], state);
            int tn = (t + 1 < SS) ? t + 1 : t;
            pf_ct = g_ct[idx0 + (size_t)tn*DD];
        }
        __syncthreads();
    }
}

// ------------------------- launch -------------------------------------------
extern "C" void kernel_launch(void* const* d_in, const int* in_sizes, int n_in,
                              void* d_out, int out_size)
{
    const float* q     = (const float*)d_in[0];
    const float* k     = (const float*)d_in[1];
    const float* v     = (const float*)d_in[2];
    const float* Wi    = (const float*)d_in[3];
    const float* bi    = (const float*)d_in[4];
    const float* Wg    = (const float*)d_in[5];
    const float* bg    = (const float*)d_in[6];
    const float* A     = (const float*)d_in[7];
    const float* Bm    = (const float*)d_in[8];
    const float* Wo    = (const float*)d_in[9];
    const float* bo    = (const float*)d_in[10];
    const float* decay = (const float*)d_in[11];
    float* out = (float*)d_out;

    void *p_ret, *p_inp, *p_gl, *p_ct, *p_st;
    cudaGetSymbolAddress(&p_ret, g_ret);
    cudaGetSymbolAddress(&p_inp, g_inp);
    cudaGetSymbolAddress(&p_gl,  g_gl);
    cudaGetSymbolAddress(&p_ct,  g_ct);
    cudaGetSymbolAddress(&p_st,  g_st);

    k_reset<<<1, 128>>>();

    k_scan1<<<(BD*NC)/256, 256>>>(k, v, decay);
    k_scan2<<<BD/256, 256>>>(decay);
    k_scan3<<<(BD*NC)/256, 256>>>(q, k, v, decay);

    dim3 gg(DD/128, MT/128);   // (N tiles, M tiles)
    // inp = retained @ Wi.T + bi
    k_gemm<<<gg, 256>>>((const float*)p_ret, Wi, bi, (float*)p_inp, MT, DD, DD, 1);
    // gate logits = inp @ Wg.T + bg
    k_gemm<<<gg, 256>>>((const float*)p_inp, Wg, bg, (float*)p_gl, MT, DD, DD, 1);
    // ct = inp @ Bm.T
    k_gemm<<<gg, 256>>>((const float*)p_inp, Bm, (const float*)0, (float*)p_ct, MT, DD, DD, 0);

    // sequential recurrence over S steps
    k_recur<<<RP, 256>>>(A);

    // out = state @ Wo.T + bo
    k_gemm<<<gg, 256>>>((const float*)p_st, Wo, bo, out, MT, DD, DD, 1);
}

// round 5
// speedup vs baseline: 2.1471x; 1.9785x over previous
#include <cuda_runtime.h>
#include <math.h>

#define BB 4
#define SS 2048
#define DD 1024
#define BD (BB*DD)          // 4096
#define MT (BB*SS)          // 8192
#define CH 128
#define NC (SS/CH)          // 16

#define RP   128            // persistent CTAs in recurrence
#define RR   (DD/RP)        // 8 rows per CTA

// ------------------------- scratch (device globals; no allocation) ---------
__device__ float g_ret[(size_t)MT*DD];
__device__ float g_inp[(size_t)MT*DD];
__device__ float g_gl [(size_t)MT*DD];
__device__ float g_ct [(size_t)MT*DD];
__device__ float g_st [(size_t)MT*DD];
__device__ float g_chend[BD*NC];
__device__ float g_carry[BD*NC];
__device__ float g_blend[2*BD];
__device__ unsigned g_bar;

// ------------------------- helpers ------------------------------------------
__device__ __forceinline__ void cp_async16(unsigned dst, const void* src) {
    asm volatile("cp.async.cg.shared.global [%0], [%1], 16;" :: "r"(dst), "l"(src));
}
#define CP_COMMIT() asm volatile("cp.async.commit_group;")
#define CP_WAIT1()  asm volatile("cp.async.wait_group 1;")
#define CP_WAIT0()  asm volatile("cp.async.wait_group 0;")

__device__ __forceinline__ unsigned f2tf32(float x) {
    unsigned u; asm("cvt.rna.tf32.f32 %0, %1;" : "=r"(u) : "f"(x)); return u;
}
__device__ __forceinline__ void mma_tf32(float* c, const unsigned* a, const unsigned* b) {
    asm volatile(
        "mma.sync.aligned.m16n8k8.row.col.f32.tf32.tf32.f32 "
        "{%0,%1,%2,%3}, {%4,%5,%6,%7}, {%8,%9}, {%0,%1,%2,%3};"
        : "+f"(c[0]), "+f"(c[1]), "+f"(c[2]), "+f"(c[3])
        : "r"(a[0]), "r"(a[1]), "r"(a[2]), "r"(a[3]), "r"(b[0]), "r"(b[1]));
}

// ------------------------- misc ---------------------------------------------
__global__ void k_reset() { g_bar = 0u; }

// ------------------------- retention scan (chunked parallel scan) ----------
__global__ void k_scan1(const float* __restrict__ k, const float* __restrict__ v,
                        const float* __restrict__ decay)
{
    int g = blockIdx.x * blockDim.x + threadIdx.x;
    int d    = g & (DD-1);
    int rest = g >> 10;
    int ch   = rest & (NC-1);
    int b    = rest >> 4;
    float dec = decay[d >> 6];
    size_t base = ((size_t)(b*SS + ch*CH))*DD + d;
    float r = 0.f;
#pragma unroll 4
    for (int t = 0; t < CH; t++) {
        r = dec*r + k[base + (size_t)t*DD] * v[base + (size_t)t*DD];
    }
    g_chend[(b*NC + ch)*DD + d] = r;
}

__global__ void k_scan2(const float* __restrict__ decay)
{
    int g = blockIdx.x * blockDim.x + threadIdx.x;
    int d = g & (DD-1);
    int b = g >> 10;
    float dec = decay[d >> 6];
    float dL = dec;
#pragma unroll
    for (int i = 0; i < 7; i++) dL *= dL;   // dec^128
    float r = 0.f;
#pragma unroll
    for (int ch = 0; ch < NC; ch++) {
        g_carry[(b*NC + ch)*DD + d] = r;
        r = g_chend[(b*NC + ch)*DD + d] + dL * r;
    }
}

__global__ void k_scan3(const float* __restrict__ q, const float* __restrict__ k,
                        const float* __restrict__ v, const float* __restrict__ decay)
{
    int g = blockIdx.x * blockDim.x + threadIdx.x;
    int d    = g & (DD-1);
    int rest = g >> 10;
    int ch   = rest & (NC-1);
    int b    = rest >> 4;
    float dec = decay[d >> 6];
    float r = g_carry[(b*NC + ch)*DD + d];
    size_t base = ((size_t)(b*SS + ch*CH))*DD + d;
#pragma unroll 4
    for (int t = 0; t < CH; t++) {
        size_t o = base + (size_t)t*DD;
        r = dec*r + k[o]*v[o];
        g_ret[o] = q[o]*r;
    }
}

// ------------------------- TF32-split tensor-core GEMM ----------------------
// C[M,N] = Act[M,K] @ W[N,K]^T (+bias).  CTA tile 128x128, K-chunk 16.
// 8 warps: wm = wid&3 (32 rows), wn = wid>>2 (64 cols). Per warp: 2 m16 x 8 n8.
// Split per operand: hi = tf32(x), lo = tf32(x - hi); acc += hi*hi+hi*lo+lo*hi.
// SMEM row stride 20 floats -> conflict-free for both A and B fragment reads.
#define GBK  16
#define GSTR 20

__global__ __launch_bounds__(256)
void k_gemm(const float* __restrict__ Act, const float* __restrict__ W,
            const float* __restrict__ bias, float* __restrict__ C,
            int M, int N, int K, int hasBias)
{
    __shared__ float As[2][128*GSTR];
    __shared__ float Bs[2][128*GSTR];
    int tid  = threadIdx.x;
    int wid  = tid >> 5;
    int lane = tid & 31;
    int g    = lane >> 2;        // groupID
    int tig  = lane & 3;         // thread in group
    int wm   = wid & 3;          // m-subtile (32 rows)
    int wn   = wid >> 2;         // n-subtile (64 cols)

    const float* Ab = Act + (size_t)blockIdx.y * 128 * K;
    const float* Wb = W   + (size_t)blockIdx.x * 128 * K;
    unsigned sA0 = (unsigned)__cvta_generic_to_shared(&As[0][0]);
    unsigned sB0 = (unsigned)__cvta_generic_to_shared(&Bs[0][0]);

    float acc[2][8][4];
#pragma unroll
    for (int mt = 0; mt < 2; mt++)
#pragma unroll
        for (int nt = 0; nt < 8; nt++)
#pragma unroll
            for (int i = 0; i < 4; i++) acc[mt][nt][i] = 0.f;

    auto loadTile = [&](int buf, int k0) {
        int f = tid * 2;                   // 512 float4 per operand tile
#pragma unroll
        for (int i2 = 0; i2 < 2; i2++) {
            int ff  = f + i2;              // 0..511
            int row = ff >> 2;
            int c4  = (ff & 3) * 4;
            cp_async16(sA0 + (unsigned)(buf*128*GSTR + row*GSTR + c4)*4u,
                       Ab + (size_t)row*K + k0 + c4);
            cp_async16(sB0 + (unsigned)(buf*128*GSTR + row*GSTR + c4)*4u,
                       Wb + (size_t)row*K + k0 + c4);
        }
    };

    int nk = K / GBK;
    loadTile(0, 0);
    CP_COMMIT();

    for (int kt = 0; kt < nk; kt++) {
        if (kt + 1 < nk) { loadTile((kt+1) & 1, (kt+1)*GBK); CP_COMMIT(); CP_WAIT1(); }
        else             { CP_WAIT0(); }
        __syncthreads();

        const float* Abs = &As[kt & 1][0];
        const float* Bbs = &Bs[kt & 1][0];
#pragma unroll
        for (int ks = 0; ks < GBK/8; ks++) {
            int kb = ks*8;
            unsigned ah[2][4], al[2][4];
#pragma unroll
            for (int mt = 0; mt < 2; mt++) {
                int rb = wm*32 + mt*16;
                float f0 = Abs[(rb + g    )*GSTR + kb + tig    ];
                float f1 = Abs[(rb + g + 8)*GSTR + kb + tig    ];
                float f2 = Abs[(rb + g    )*GSTR + kb + tig + 4];
                float f3 = Abs[(rb + g + 8)*GSTR + kb + tig + 4];
                ah[mt][0] = f2tf32(f0); al[mt][0] = f2tf32(f0 - __uint_as_float(ah[mt][0]));
                ah[mt][1] = f2tf32(f1); al[mt][1] = f2tf32(f1 - __uint_as_float(ah[mt][1]));
                ah[mt][2] = f2tf32(f2); al[mt][2] = f2tf32(f2 - __uint_as_float(ah[mt][2]));
                ah[mt][3] = f2tf32(f3); al[mt][3] = f2tf32(f3 - __uint_as_float(ah[mt][3]));
            }
            unsigned bh[8][2], bl[8][2];
#pragma unroll
            for (int nt = 0; nt < 8; nt++) {
                int nb = wn*64 + nt*8;
                float f0 = Bbs[(nb + g)*GSTR + kb + tig    ];
                float f1 = Bbs[(nb + g)*GSTR + kb + tig + 4];
                bh[nt][0] = f2tf32(f0); bl[nt][0] = f2tf32(f0 - __uint_as_float(bh[nt][0]));
                bh[nt][1] = f2tf32(f1); bl[nt][1] = f2tf32(f1 - __uint_as_float(bh[nt][1]));
            }
#pragma unroll
            for (int mt = 0; mt < 2; mt++)
#pragma unroll
                for (int nt = 0; nt < 8; nt++) {
                    mma_tf32(acc[mt][nt], ah[mt], bh[nt]);
                    mma_tf32(acc[mt][nt], ah[mt], bl[nt]);
                    mma_tf32(acc[mt][nt], al[mt], bh[nt]);
                }
        }
        __syncthreads();
    }

    // epilogue
#pragma unroll
    for (int mt = 0; mt < 2; mt++) {
        int r0 = blockIdx.y*128 + wm*32 + mt*16 + g;
#pragma unroll
        for (int nt = 0; nt < 8; nt++) {
            int c0 = blockIdx.x*128 + wn*64 + nt*8 + 2*tig;
            float b0 = hasBias ? bias[c0]     : 0.f;
            float b1 = hasBias ? bias[c0 + 1] : 0.f;
            float2 o0 = make_float2(acc[mt][nt][0] + b0, acc[mt][nt][1] + b1);
            float2 o1 = make_float2(acc[mt][nt][2] + b0, acc[mt][nt][3] + b1);
            *(float2*)(C + (size_t)r0      *N + c0) = o0;
            *(float2*)(C + (size_t)(r0 + 8)*N + c0) = o1;
        }
    }
}

// ------------------------- sequential state recurrence ----------------------
// EXACTLY the R1 structure (proven): single atomic counter barrier, one
// polling thread per CTA with nanosleep backoff.
__global__ __launch_bounds__(256, 1)
void k_recur(const float* __restrict__ Amat)
{
    __shared__ float bl_s[4][1032];   // padded: conflict-free broadcast
    __shared__ float part[8][32];
    __shared__ float st_s[32];

    int tid  = threadIdx.x;
    int cta  = blockIdx.x;
    int row0 = cta * RR;
    int w    = tid >> 5;              // warp = k-chunk of 128
    int lane = tid & 31;
    int lr   = lane >> 2;             // local row 0..7
    int bo   = lane & 3;              // batch 0..3

    // A slice into registers: A[row0+lr][w*128 .. w*128+127]
    float4 a4[32];
    {
        const float* Arow = Amat + (size_t)(row0 + lr)*DD + w*128;
#pragma unroll
        for (int i = 0; i < 32; i++) a4[i] = *(const float4*)(Arow + i*4);
    }
    if (tid < 32) st_s[tid] = 0.f;
    __syncthreads();

    for (int t = 0; t < SS; t++) {
        // 1) blended slice: bl = inp + gate*(state - inp)
        if (tid < 32) {
            int l2 = tid >> 2, b2 = tid & 3;
            size_t gi = ((size_t)(b2*SS + t))*DD + row0 + l2;
            float glv = g_gl[gi];
            float ip  = g_inp[gi];
            float gate = 1.f / (1.f + expf(-glv));
            float bl = fmaf(gate, st_s[tid] - ip, ip);
            g_blend[(t & 1)*BD + b2*DD + row0 + l2] = bl;
        }
        __syncthreads();

        // 2) grid barrier (counting, reset by k_reset each launch)
        if (tid == 0) {
            __threadfence();
            atomicAdd(&g_bar, 1u);
            unsigned target = (unsigned)(t + 1) * RP;
            while (*(volatile unsigned*)&g_bar < target) { __nanosleep(32); }
            __threadfence();
        }
        __syncthreads();

        // 3) stage full blended vector into SMEM (bypass L1: buffer reused)
        {
            const float4* src = (const float4*)(g_blend + (t & 1)*BD);
#pragma unroll
            for (int i = 0; i < 4; i++) {
                int idx = tid + i*256;            // 1024 float4
                float4 vv = __ldcg(src + idx);
                int b2 = idx >> 8;
                int k4 = (idx & 255) * 4;
                *(float4*)&bl_s[b2][k4] = vv;
            }
        }
        __syncthreads();

        // 4) register-A GEMV over this warp's k-chunk
        {
            const float4* xb = (const float4*)&bl_s[bo][w*128];
            float s0 = 0.f, s1 = 0.f, s2 = 0.f, s3 = 0.f;
#pragma unroll
            for (int i = 0; i < 32; i++) {
                float4 x = xb[i];
                s0 = fmaf(a4[i].x, x.x, s0);
                s1 = fmaf(a4[i].y, x.y, s1);
                s2 = fmaf(a4[i].z, x.z, s2);
                s3 = fmaf(a4[i].w, x.w, s3);
            }
            part[w][lane] = (s0 + s1) + (s2 + s3);
        }
        __syncthreads();

        // 5) reduce 8 k-chunks, add Bm-term, tanh, commit state
        if (tid < 32) {
            float s = 0.f;
#pragma unroll
            for (int ww = 0; ww < 8; ww++) s += part[ww][tid];
            int l2 = tid >> 2, b2 = tid & 3;
            size_t gi = ((size_t)(b2*SS + t))*DD + row0 + l2;
            float ns = tanhf(s + g_ct[gi]);
            st_s[tid] = ns;
            g_st[gi] = ns;
        }
        __syncthreads();
    }
}

// ------------------------- launch -------------------------------------------
extern "C" void kernel_launch(void* const* d_in, const int* in_sizes, int n_in,
                              void* d_out, int out_size)
{
    const float* q     = (const float*)d_in[0];
    const float* k     = (const float*)d_in[1];
    const float* v     = (const float*)d_in[2];
    const float* Wi    = (const float*)d_in[3];
    const float* bi    = (const float*)d_in[4];
    const float* Wg    = (const float*)d_in[5];
    const float* bg    = (const float*)d_in[6];
    const float* A     = (const float*)d_in[7];
    const float* Bm    = (const float*)d_in[8];
    const float* Wo    = (const float*)d_in[9];
    const float* bo    = (const float*)d_in[10];
    const float* decay = (const float*)d_in[11];
    float* out = (float*)d_out;

    void *p_ret, *p_inp, *p_gl, *p_ct, *p_st;
    cudaGetSymbolAddress(&p_ret, g_ret);
    cudaGetSymbolAddress(&p_inp, g_inp);
    cudaGetSymbolAddress(&p_gl,  g_gl);
    cudaGetSymbolAddress(&p_ct,  g_ct);
    cudaGetSymbolAddress(&p_st,  g_st);

    k_reset<<<1, 1>>>();

    k_scan1<<<(BD*NC)/256, 256>>>(k, v, decay);
    k_scan2<<<BD/256, 256>>>(decay);
    k_scan3<<<(BD*NC)/256, 256>>>(q, k, v, decay);

    dim3 gg(DD/128, MT/128);   // (N tiles, M tiles)
    // inp = retained @ Wi.T + bi
    k_gemm<<<gg, 256>>>((const float*)p_ret, Wi, bi, (float*)p_inp, MT, DD, DD, 1);
    // gate logits = inp @ Wg.T + bg
    k_gemm<<<gg, 256>>>((const float*)p_inp, Wg, bg, (float*)p_gl, MT, DD, DD, 1);
    // ct = inp @ Bm.T
    k_gemm<<<gg, 256>>>((const float*)p_inp, Bm, (const float*)0, (float*)p_ct, MT, DD, DD, 0);

    // sequential recurrence over S steps
    k_recur<<<RP, 256>>>(A);

    // out = state @ Wo.T + bo
    k_gemm<<<gg, 256>>>((const float*)p_st, Wo, bo, out, MT, DD, DD, 1);
}

// round 6
// speedup vs baseline: 2.3878x; 1.1121x over previous
#include <cuda_runtime.h>
#include <math.h>

#define BB 4
#define SS 2048
#define DD 1024
#define BD (BB*DD)          // 4096
#define MT (BB*SS)          // 8192
#define CH 128
#define NC (SS/CH)          // 16

#define RP   128            // persistent CTAs in recurrence
#define RR   (DD/RP)        // 8 rows per CTA

typedef unsigned long long ull;

// ------------------------- scratch (device globals; no allocation) ---------
__device__ float g_ret[(size_t)MT*DD];
__device__ float g_inp[(size_t)MT*DD];
__device__ float g_gl [(size_t)MT*DD];
__device__ float g_ct [(size_t)MT*DD];
__device__ float g_st [(size_t)MT*DD];
__device__ float g_chend[BD*NC];
__device__ float g_carry[BD*NC];
__device__ float g_blend[2*BD];
__device__ unsigned g_bar;

// ------------------------- helpers ------------------------------------------
__device__ __forceinline__ void cp_async16(unsigned dst, const void* src) {
    asm volatile("cp.async.cg.shared.global [%0], [%1], 16;" :: "r"(dst), "l"(src));
}
#define CP_COMMIT() asm volatile("cp.async.commit_group;")
#define CP_WAIT1()  asm volatile("cp.async.wait_group 1;")
#define CP_WAIT0()  asm volatile("cp.async.wait_group 0;")

__device__ __forceinline__ unsigned f2tf32(float x) {
    unsigned u; asm("cvt.rna.tf32.f32 %0, %1;" : "=r"(u) : "f"(x)); return u;
}
__device__ __forceinline__ void mma_tf32(float* c, const unsigned* a, const unsigned* b) {
    asm volatile(
        "mma.sync.aligned.m16n8k8.row.col.f32.tf32.tf32.f32 "
        "{%0,%1,%2,%3}, {%4,%5,%6,%7}, {%8,%9}, {%0,%1,%2,%3};"
        : "+f"(c[0]), "+f"(c[1]), "+f"(c[2]), "+f"(c[3])
        : "r"(a[0]), "r"(a[1]), "r"(a[2]), "r"(a[3]), "r"(b[0]), "r"(b[1]));
}
__device__ __forceinline__ void ffma2(ull& d, ull a, ull b) {
    asm volatile("fma.rn.f32x2 %0, %1, %2, %0;" : "+l"(d) : "l"(a), "l"(b));
}
__device__ __forceinline__ float2 unpack2(ull v) {
    float2 f; asm("mov.b64 {%0, %1}, %2;" : "=f"(f.x), "=f"(f.y) : "l"(v)); return f;
}
__device__ __forceinline__ float fsigmoid(float x) {
    return __fdividef(1.f, 1.f + __expf(-x));
}
__device__ __forceinline__ float ftanh(float x) {
    x = fminf(fmaxf(x, -15.f), 15.f);
    float e = __expf(2.f * x);
    return __fdividef(e - 1.f, e + 1.f);
}

// ------------------------- misc ---------------------------------------------
__global__ void k_reset() { g_bar = 0u; }

// ------------------------- retention scan (chunked parallel scan) ----------
__global__ void k_scan1(const float* __restrict__ k, const float* __restrict__ v,
                        const float* __restrict__ decay)
{
    int g = blockIdx.x * blockDim.x + threadIdx.x;
    int d    = g & (DD-1);
    int rest = g >> 10;
    int ch   = rest & (NC-1);
    int b    = rest >> 4;
    float dec = decay[d >> 6];
    size_t base = ((size_t)(b*SS + ch*CH))*DD + d;
    float r = 0.f;
#pragma unroll 4
    for (int t = 0; t < CH; t++) {
        r = dec*r + k[base + (size_t)t*DD] * v[base + (size_t)t*DD];
    }
    g_chend[(b*NC + ch)*DD + d] = r;
}

__global__ void k_scan2(const float* __restrict__ decay)
{
    int g = blockIdx.x * blockDim.x + threadIdx.x;
    int d = g & (DD-1);
    int b = g >> 10;
    float dec = decay[d >> 6];
    float dL = dec;
#pragma unroll
    for (int i = 0; i < 7; i++) dL *= dL;   // dec^128
    float r = 0.f;
#pragma unroll
    for (int ch = 0; ch < NC; ch++) {
        g_carry[(b*NC + ch)*DD + d] = r;
        r = g_chend[(b*NC + ch)*DD + d] + dL * r;
    }
}

__global__ void k_scan3(const float* __restrict__ q, const float* __restrict__ k,
                        const float* __restrict__ v, const float* __restrict__ decay)
{
    int g = blockIdx.x * blockDim.x + threadIdx.x;
    int d    = g & (DD-1);
    int rest = g >> 10;
    int ch   = rest & (NC-1);
    int b    = rest >> 4;
    float dec = decay[d >> 6];
    float r = g_carry[(b*NC + ch)*DD + d];
    size_t base = ((size_t)(b*SS + ch*CH))*DD + d;
#pragma unroll 4
    for (int t = 0; t < CH; t++) {
        size_t o = base + (size_t)t*DD;
        r = dec*r + k[o]*v[o];
        g_ret[o] = q[o]*r;
    }
}

// ------------------------- TF32-split tensor-core GEMM (unchanged, R4) ------
#define GBK  16
#define GSTR 20

__global__ __launch_bounds__(256)
void k_gemm(const float* __restrict__ Act, const float* __restrict__ W,
            const float* __restrict__ bias, float* __restrict__ C,
            int M, int N, int K, int hasBias)
{
    __shared__ float As[2][128*GSTR];
    __shared__ float Bs[2][128*GSTR];
    int tid  = threadIdx.x;
    int wid  = tid >> 5;
    int lane = tid & 31;
    int g    = lane >> 2;
    int tig  = lane & 3;
    int wm   = wid & 3;
    int wn   = wid >> 2;

    const float* Ab = Act + (size_t)blockIdx.y * 128 * K;
    const float* Wb = W   + (size_t)blockIdx.x * 128 * K;
    unsigned sA0 = (unsigned)__cvta_generic_to_shared(&As[0][0]);
    unsigned sB0 = (unsigned)__cvta_generic_to_shared(&Bs[0][0]);

    float acc[2][8][4];
#pragma unroll
    for (int mt = 0; mt < 2; mt++)
#pragma unroll
        for (int nt = 0; nt < 8; nt++)
#pragma unroll
            for (int i = 0; i < 4; i++) acc[mt][nt][i] = 0.f;

    auto loadTile = [&](int buf, int k0) {
        int f = tid * 2;
#pragma unroll
        for (int i2 = 0; i2 < 2; i2++) {
            int ff  = f + i2;
            int row = ff >> 2;
            int c4  = (ff & 3) * 4;
            cp_async16(sA0 + (unsigned)(buf*128*GSTR + row*GSTR + c4)*4u,
                       Ab + (size_t)row*K + k0 + c4);
            cp_async16(sB0 + (unsigned)(buf*128*GSTR + row*GSTR + c4)*4u,
                       Wb + (size_t)row*K + k0 + c4);
        }
    };

    int nk = K / GBK;
    loadTile(0, 0);
    CP_COMMIT();

    for (int kt = 0; kt < nk; kt++) {
        if (kt + 1 < nk) { loadTile((kt+1) & 1, (kt+1)*GBK); CP_COMMIT(); CP_WAIT1(); }
        else             { CP_WAIT0(); }
        __syncthreads();

        const float* Abs = &As[kt & 1][0];
        const float* Bbs = &Bs[kt & 1][0];
#pragma unroll
        for (int ks = 0; ks < GBK/8; ks++) {
            int kb = ks*8;
            unsigned ah[2][4], al[2][4];
#pragma unroll
            for (int mt = 0; mt < 2; mt++) {
                int rb = wm*32 + mt*16;
                float f0 = Abs[(rb + g    )*GSTR + kb + tig    ];
                float f1 = Abs[(rb + g + 8)*GSTR + kb + tig    ];
                float f2 = Abs[(rb + g    )*GSTR + kb + tig + 4];
                float f3 = Abs[(rb + g + 8)*GSTR + kb + tig + 4];
                ah[mt][0] = f2tf32(f0); al[mt][0] = f2tf32(f0 - __uint_as_float(ah[mt][0]));
                ah[mt][1] = f2tf32(f1); al[mt][1] = f2tf32(f1 - __uint_as_float(ah[mt][1]));
                ah[mt][2] = f2tf32(f2); al[mt][2] = f2tf32(f2 - __uint_as_float(ah[mt][2]));
                ah[mt][3] = f2tf32(f3); al[mt][3] = f2tf32(f3 - __uint_as_float(ah[mt][3]));
            }
            unsigned bh[8][2], bl[8][2];
#pragma unroll
            for (int nt = 0; nt < 8; nt++) {
                int nb = wn*64 + nt*8;
                float f0 = Bbs[(nb + g)*GSTR + kb + tig    ];
                float f1 = Bbs[(nb + g)*GSTR + kb + tig + 4];
                bh[nt][0] = f2tf32(f0); bl[nt][0] = f2tf32(f0 - __uint_as_float(bh[nt][0]));
                bh[nt][1] = f2tf32(f1); bl[nt][1] = f2tf32(f1 - __uint_as_float(bh[nt][1]));
            }
#pragma unroll
            for (int mt = 0; mt < 2; mt++)
#pragma unroll
                for (int nt = 0; nt < 8; nt++) {
                    mma_tf32(acc[mt][nt], ah[mt], bh[nt]);
                    mma_tf32(acc[mt][nt], ah[mt], bl[nt]);
                    mma_tf32(acc[mt][nt], al[mt], bh[nt]);
                }
        }
        __syncthreads();
    }

#pragma unroll
    for (int mt = 0; mt < 2; mt++) {
        int r0 = blockIdx.y*128 + wm*32 + mt*16 + g;
#pragma unroll
        for (int nt = 0; nt < 8; nt++) {
            int c0 = blockIdx.x*128 + wn*64 + nt*8 + 2*tig;
            float b0 = hasBias ? bias[c0]     : 0.f;
            float b1 = hasBias ? bias[c0 + 1] : 0.f;
            float2 o0 = make_float2(acc[mt][nt][0] + b0, acc[mt][nt][1] + b1);
            float2 o1 = make_float2(acc[mt][nt][2] + b0, acc[mt][nt][3] + b1);
            *(float2*)(C + (size_t)r0      *N + c0) = o0;
            *(float2*)(C + (size_t)(r0 + 8)*N + c0) = o1;
        }
    }
}

// ------------------------- sequential state recurrence ----------------------
// R1/R4 barrier kept verbatim (single atomic counter, one nanosleep poller
// per CTA). New: register prefetch of g_gl/g_inp/g_ct one step ahead (DRAM
// latency off the serial chain), state held in warp0 registers, 3 syncs/step,
// MUFU sigmoid/tanh, FFMA2 GEMV.
__global__ __launch_bounds__(256, 1)
void k_recur(const float* __restrict__ Amat)
{
    __shared__ float bl_s[4][1032];   // padded: conflict-free GEMV broadcast
    __shared__ float part[8][32];

    int tid  = threadIdx.x;
    int cta  = blockIdx.x;
    int row0 = cta * RR;
    int w    = tid >> 5;              // warp = k-chunk of 128
    int lane = tid & 31;
    int lr   = lane >> 2;             // local row 0..7
    int bo   = lane & 3;              // batch 0..3

    // A slice in registers, k-pair packed: A[row0+lr][w*128 .. +127]
    ull a2[64];
    {
        const ulonglong2* Ar =
            (const ulonglong2*)(Amat + (size_t)(row0 + lr)*DD + w*128);
#pragma unroll
        for (int i = 0; i < 32; i++) {
            ulonglong2 u = Ar[i];
            a2[2*i]   = u.x;
            a2[2*i+1] = u.y;
        }
    }

    int b2 = tid & 3, l2 = tid >> 2;          // meaningful for tid<32
    size_t idx0 = ((size_t)b2*SS)*DD + row0 + l2;
    float state = 0.f;
    float pf_gl = 0.f, pf_inp = 0.f, pf_ct = 0.f;
    if (tid < 32) {
        pf_gl  = g_gl [idx0];
        pf_inp = g_inp[idx0];
        pf_ct  = g_ct [idx0];
    }
    __syncthreads();

    for (int t = 0; t < SS; t++) {
        // 1) warp 0: blend + publish, issue t+1 prefetches, arrive + poll
        if (tid < 32) {
            float gate = fsigmoid(pf_gl);
            float bl = fmaf(gate, state - pf_inp, pf_inp);
            __stcg(&g_blend[(t & 1)*BD + b2*DD + row0 + l2], bl);
            __syncwarp();
            // prefetch next step's gate logits / inp (hidden by barrier+GEMV)
            int tn = (t + 1 < SS) ? t + 1 : t;
            size_t nidx = idx0 + (size_t)tn*DD;
            pf_gl  = g_gl [nidx];
            pf_inp = g_inp[nidx];
            if (tid == 0) {
                __threadfence();
                atomicAdd(&g_bar, 1u);
                unsigned target = (unsigned)(t + 1) * RP;
                while (*(volatile unsigned*)&g_bar < target) { __nanosleep(32); }
                __threadfence();
            }
        }
        __syncthreads();   // syncA: barrier passed

        // 2) stage full blended vector into SMEM (L1-bypassed)
        {
            const float4* src = (const float4*)(g_blend + (t & 1)*BD);
#pragma unroll
            for (int i = 0; i < 4; i++) {
                int idx = tid + i*256;            // 1024 float4
                float4 vv = __ldcg(src + idx);
                int bb = idx >> 8;
                int k4 = (idx & 255) * 4;
                *(float4*)&bl_s[bb][k4] = vv;
            }
        }
        __syncthreads();   // syncB: tile staged

        // 3) register-A GEMV over this warp's k-chunk (packed f32x2)
        {
            const ulonglong2* xb = (const ulonglong2*)&bl_s[bo][w*128];
            ull s0 = 0ull, s1 = 0ull;
#pragma unroll
            for (int i = 0; i < 32; i++) {
                ulonglong2 x = xb[i];
                ffma2(s0, a2[2*i],   x.x);
                ffma2(s1, a2[2*i+1], x.y);
            }
            float2 p0 = unpack2(s0), p1 = unpack2(s1);
            part[w][lane] = (p0.x + p0.y) + (p1.x + p1.y);
        }
        __syncthreads();   // syncC: partials ready

        // 4) warp 0: reduce, add Bm-term, tanh, commit; prefetch next ct.
        //    (No trailing sync: other warps wait at syncA of t+1.)
        if (tid < 32) {
            float s = pf_ct;
#pragma unroll
            for (int ww = 0; ww < 8; ww++) s += part[ww][tid];
            state = ftanh(s);
            __stcg(&g_st[idx0 + (size_t)t*DD], state);
            int tn = (t + 1 < SS) ? t + 1 : t;
            pf_ct = g_ct[idx0 + (size_t)tn*DD];
        }
    }
}

// ------------------------- launch -------------------------------------------
extern "C" void kernel_launch(void* const* d_in, const int* in_sizes, int n_in,
                              void* d_out, int out_size)
{
    const float* q     = (const float*)d_in[0];
    const float* k     = (const float*)d_in[1];
    const float* v     = (const float*)d_in[2];
    const float* Wi    = (const float*)d_in[3];
    const float* bi    = (const float*)d_in[4];
    const float* Wg    = (const float*)d_in[5];
    const float* bg    = (const float*)d_in[6];
    const float* A     = (const float*)d_in[7];
    const float* Bm    = (const float*)d_in[8];
    const float* Wo    = (const float*)d_in[9];
    const float* bo    = (const float*)d_in[10];
    const float* decay = (const float*)d_in[11];
    float* out = (float*)d_out;

    void *p_ret, *p_inp, *p_gl, *p_ct, *p_st;
    cudaGetSymbolAddress(&p_ret, g_ret);
    cudaGetSymbolAddress(&p_inp, g_inp);
    cudaGetSymbolAddress(&p_gl,  g_gl);
    cudaGetSymbolAddress(&p_ct,  g_ct);
    cudaGetSymbolAddress(&p_st,  g_st);

    k_reset<<<1, 1>>>();

    k_scan1<<<(BD*NC)/256, 256>>>(k, v, decay);
    k_scan2<<<BD/256, 256>>>(decay);
    k_scan3<<<(BD*NC)/256, 256>>>(q, k, v, decay);

    dim3 gg(DD/128, MT/128);   // (N tiles, M tiles)
    k_gemm<<<gg, 256>>>((const float*)p_ret, Wi, bi, (float*)p_inp, MT, DD, DD, 1);
    k_gemm<<<gg, 256>>>((const float*)p_inp, Wg, bg, (float*)p_gl, MT, DD, DD, 1);
    k_gemm<<<gg, 256>>>((const float*)p_inp, Bm, (const float*)0, (float*)p_ct, MT, DD, DD, 0);

    k_recur<<<RP, 256>>>(A);

    k_gemm<<<gg, 256>>>((const float*)p_st, Wo, bo, out, MT, DD, DD, 1);
}